// round 10
// baseline (speedup 1.0000x reference)
#include <cuda_runtime.h>
#include <cuda_bf16.h>
#include <cstdint>

// Problem constants
#define S_LEN   64
#define NBATCH  64
#define EMBD    512
#define HIDD    512
#define NVOCAB  10000
#define SB      4096            // S_LEN * NBATCH
#define LOGITS_SZ 40960000      // SB * NVOCAB
#define HFIN_SZ   65536         // 2 * NBATCH * HIDD

#define RCTAS   64              // CTAs per persistent recurrence layer

// Split-GEMM dims
#define GK      1536            // 3 * HIDD
#define NPAD    10240           // vocab padded to 128-multiple

// Scratch (device globals: no cudaMalloc allowed)
__device__ float g_A0[SB * HIDD];
__device__ float g_H0[SB * HIDD];
__device__ float g_A1[SB * HIDD];
__device__ float g_H1[SB * HIDD];
__device__ int   g_ctr[2 * S_LEN];              // per-step barrier counters
__device__ __nv_bfloat16 g_Ahat[SB * GK];       // [Hhi | Hhi | Hlo]
__device__ __nv_bfloat16 g_Bhat[NPAD * GK];     // [Whi | Wlo | Whi]

static __device__ __forceinline__ uint32_t smem_u32(const void* p) {
    uint32_t a;
    asm("{ .reg .u64 t; cvta.to.shared.u64 t, %1; cvt.u32.u64 %0, t; }"
        : "=r"(a) : "l"(p));
    return a;
}
static __device__ __forceinline__ void cpa16(uint32_t dst, const void* src) {
    asm volatile("cp.async.cg.shared.global [%0], [%1], 16;"
                 :: "r"(dst), "l"(src));
}
#define CP_COMMIT() asm volatile("cp.async.commit_group;")
#define CP_WAIT(N_) asm volatile("cp.async.wait_group %0;" :: "n"(N_))

static __device__ __forceinline__ void ldm_x4(uint32_t& r0, uint32_t& r1,
                                              uint32_t& r2, uint32_t& r3,
                                              uint32_t addr) {
    asm volatile("ldmatrix.sync.aligned.m8n8.x4.shared.b16 {%0,%1,%2,%3}, [%4];"
                 : "=r"(r0), "=r"(r1), "=r"(r2), "=r"(r3) : "r"(addr));
}
static __device__ __forceinline__ void mma_bf16(float4& d,
                                                uint32_t a0, uint32_t a1,
                                                uint32_t a2, uint32_t a3,
                                                uint32_t b0, uint32_t b1) {
    asm volatile("mma.sync.aligned.m16n8k16.row.col.f32.bf16.bf16.f32 "
                 "{%0,%1,%2,%3}, {%4,%5,%6,%7}, {%8,%9}, {%0,%1,%2,%3};"
                 : "+f"(d.x), "+f"(d.y), "+f"(d.z), "+f"(d.w)
                 : "r"(a0), "r"(a1), "r"(a2), "r"(a3), "r"(b0), "r"(b1));
}

// ---------------------------------------------------------------------------
// Generic NT SGEMM (fp32), used for the two small A-precompute GEMMs.
// 128x128 tile, BK=16, 256 threads, 8x8 microtile, double-buffered SMEM.
// ---------------------------------------------------------------------------
template <bool GATHER>
__global__ __launch_bounds__(256)
void sgemm_nt(const float* __restrict__ A, const int* __restrict__ tok,
              const float* __restrict__ B,
              const float* __restrict__ bias1, const float* __restrict__ bias2,
              float* __restrict__ C, int N, int K, int ldc)
{
    __shared__ float As[2][16 * 128];
    __shared__ float Bs[2][16 * 128];

    const int tid = threadIdx.x;
    const int m0  = blockIdx.y * 128;
    const int n0  = blockIdx.x * 128;
    const int tx  = tid & 15;
    const int ty  = tid >> 4;

    const int row0 = tid >> 2;
    const int row1 = row0 + 64;
    const int kq   = (tid & 3) << 2;

    const float* pa0 = GATHER ? (A + (size_t)tok[m0 + row0] * K)
                              : (A + (size_t)(m0 + row0) * K);
    const float* pa1 = GATHER ? (A + (size_t)tok[m0 + row1] * K)
                              : (A + (size_t)(m0 + row1) * K);
    const int gc0 = n0 + row0, gc1 = n0 + row1;
    const float* pb0 = B + (size_t)gc0 * K;
    const float* pb1 = B + (size_t)gc1 * K;
    const bool  v0 = (gc0 < N), v1 = (gc1 < N);

    float4 aR0, aR1, bR0, bR1;

#define LOAD_TILES(K0_)                                                        \
    do {                                                                       \
        aR0 = *(const float4*)(pa0 + (K0_) + kq);                              \
        aR1 = *(const float4*)(pa1 + (K0_) + kq);                              \
        bR0 = v0 ? *(const float4*)(pb0 + (K0_) + kq)                          \
                 : make_float4(0.f, 0.f, 0.f, 0.f);                            \
        bR1 = v1 ? *(const float4*)(pb1 + (K0_) + kq)                          \
                 : make_float4(0.f, 0.f, 0.f, 0.f);                            \
    } while (0)

#define STORE_TILES(BUF_)                                                      \
    do {                                                                       \
        float* Ad = As[BUF_];                                                  \
        float* Bd = Bs[BUF_];                                                  \
        {                                                                      \
            int ph = ((row0 >> 2) ^ (kq >> 2));                                \
            int b  = kq * 128 + (ph << 2) + (row0 & 3);                        \
            Ad[b] = aR0.x; Ad[b + 128] = aR0.y;                                \
            Ad[b + 256] = aR0.z; Ad[b + 384] = aR0.w;                          \
            Bd[b] = bR0.x; Bd[b + 128] = bR0.y;                                \
            Bd[b + 256] = bR0.z; Bd[b + 384] = bR0.w;                          \
        }                                                                      \
        {                                                                      \
            int ph = ((row1 >> 2) ^ (kq >> 2));                                \
            int b  = kq * 128 + (ph << 2) + (row1 & 3);                        \
            Ad[b] = aR1.x; Ad[b + 128] = aR1.y;                                \
            Ad[b + 256] = aR1.z; Ad[b + 384] = aR1.w;                          \
            Bd[b] = bR1.x; Bd[b + 128] = bR1.y;                                \
            Bd[b + 256] = bR1.z; Bd[b + 384] = bR1.w;                          \
        }                                                                      \
    } while (0)

    float acc[8][8];
#pragma unroll
    for (int i = 0; i < 8; ++i)
#pragma unroll
        for (int j = 0; j < 8; ++j) acc[i][j] = 0.f;

    LOAD_TILES(0);
    STORE_TILES(0);
    __syncthreads();

    int buf = 0;
    for (int k0 = 0; k0 < K; k0 += 16) {
        const int kn = k0 + 16;
        if (kn < K) LOAD_TILES(kn);

        const float* Ac = As[buf];
        const float* Bc = Bs[buf];
#pragma unroll
        for (int kk = 0; kk < 16; ++kk) {
            const int x = (kk >> 2);
            float4 a0 = *(const float4*)(Ac + kk * 128 + ((((ty << 1))     ^ x) << 2));
            float4 a1 = *(const float4*)(Ac + kk * 128 + ((((ty << 1) + 1) ^ x) << 2));
            float4 b0 = *(const float4*)(Bc + kk * 128 + ((((tx << 1))     ^ x) << 2));
            float4 b1 = *(const float4*)(Bc + kk * 128 + ((((tx << 1) + 1) ^ x) << 2));
            float av[8] = {a0.x, a0.y, a0.z, a0.w, a1.x, a1.y, a1.z, a1.w};
            float bv[8] = {b0.x, b0.y, b0.z, b0.w, b1.x, b1.y, b1.z, b1.w};
#pragma unroll
            for (int i = 0; i < 8; ++i)
#pragma unroll
                for (int j = 0; j < 8; ++j)
                    acc[i][j] = fmaf(av[i], bv[j], acc[i][j]);
        }

        if (kn < K) STORE_TILES(buf ^ 1);
        __syncthreads();
        buf ^= 1;
    }
#undef LOAD_TILES
#undef STORE_TILES

    float badd[8];
#pragma unroll
    for (int j = 0; j < 8; ++j) {
        int c = n0 + (tx << 3) + j;
        float b = 0.f;
        if (c < N) {
            b = bias1[c];
            if (bias2) b += bias2[c];
        }
        badd[j] = b;
    }

#pragma unroll
    for (int i = 0; i < 8; ++i) {
        float* crow = C + (size_t)(m0 + (ty << 3) + i) * ldc + n0 + (tx << 3);
        float4 w0 = make_float4(acc[i][0] + badd[0], acc[i][1] + badd[1],
                                acc[i][2] + badd[2], acc[i][3] + badd[3]);
        float4 w1 = make_float4(acc[i][4] + badd[4], acc[i][5] + badd[5],
                                acc[i][6] + badd[6], acc[i][7] + badd[7]);
        *(float4*)(crow)     = w0;
        *(float4*)(crow + 4) = w1;
    }
}

// ---------------------------------------------------------------------------
// Persistent recurrence layer, v3: NO H staging. Each thread streams its
// Hprev row straight from L2 via LDG.128 (lanes 0-3 dedup in L1); U slice
// (8 x 512, stride-516, 16.5 KB static SMEM) resident for the whole layer.
// Per step: LDG-stream + FMA, store own 8-col slice, fence, atomic counter
// barrier (tid 0 spins, short nanosleep). 64 CTAs co-resident.
// ---------------------------------------------------------------------------
#define USTRIDE 516

__global__ __launch_bounds__(256)
void rnn_layer(const float* __restrict__ Hinit,
               const float* __restrict__ U,
               const float* __restrict__ Acc,
               float* __restrict__ Hout,
               int* __restrict__ ctr)            // [S_LEN]
{
    __shared__ float Us[8 * USTRIDE];            // 16512 B

    const int tid  = threadIdx.x;
    const int n0   = blockIdx.x * 8;
    const int lane = tid & 31;
    const int row  = (tid >> 5) * 8 + (lane >> 2);   // 0..63
    const int c0   = (lane & 3) * 2;
    const int c1   = c0 + 1;

    // Load U slice once: 8 cols x 512 k
#pragma unroll
    for (int l = 0; l < 4; ++l) {
        int idx = tid + l * 256;
        int col = idx >> 7;
        int kk  = (idx & 127) << 2;
        *(float4*)(Us + col * USTRIDE + kk) =
            *(const float4*)(U + (size_t)(n0 + col) * HIDD + kk);
    }
    __syncthreads();

    const float* Hprev = Hinit;
    const float* u0p = Us + c0 * USTRIDE;
    const float* u1p = Us + c1 * USTRIDE;

    for (int s = 0; s < S_LEN; ++s) {
        const size_t base = ((size_t)(s * NBATCH + row)) * HIDD + n0;
        const float av0 = Acc[base + c0];
        const float av1 = Acc[base + c1];
        const float* hrow = Hprev + (size_t)row * HIDD;

        float a00 = 0.f, a01 = 0.f, a10 = 0.f, a11 = 0.f;
#pragma unroll 8
        for (int kk = 0; kk < HIDD; kk += 8) {
            float4 h0  = *(const float4*)(hrow + kk);       // LDG (L2)
            float4 h1  = *(const float4*)(hrow + kk + 4);
            float4 u00 = *(const float4*)(u0p + kk);        // LDS
            float4 u01 = *(const float4*)(u0p + kk + 4);
            float4 u10 = *(const float4*)(u1p + kk);
            float4 u11 = *(const float4*)(u1p + kk + 4);
            a00 = fmaf(h0.x, u00.x, a00); a00 = fmaf(h0.y, u00.y, a00);
            a00 = fmaf(h0.z, u00.z, a00); a00 = fmaf(h0.w, u00.w, a00);
            a10 = fmaf(h0.x, u10.x, a10); a10 = fmaf(h0.y, u10.y, a10);
            a10 = fmaf(h0.z, u10.z, a10); a10 = fmaf(h0.w, u10.w, a10);
            a01 = fmaf(h1.x, u01.x, a01); a01 = fmaf(h1.y, u01.y, a01);
            a01 = fmaf(h1.z, u01.z, a01); a01 = fmaf(h1.w, u01.w, a01);
            a11 = fmaf(h1.x, u11.x, a11); a11 = fmaf(h1.y, u11.y, a11);
            a11 = fmaf(h1.z, u11.z, a11); a11 = fmaf(h1.w, u11.w, a11);
        }
        Hout[base + c0] = tanhf(a00 + a01 + av0);
        Hout[base + c1] = tanhf(a10 + a11 + av1);

        // grid barrier: release own stores, count, spin, acquire
        __threadfence();
        __syncthreads();
        if (tid == 0) {
            atomicAdd(&ctr[s], 1);
            while (*(volatile int*)&ctr[s] < RCTAS) __nanosleep(32);
            __threadfence();
        }
        __syncthreads();

        Hprev = Hout + (size_t)s * NBATCH * HIDD;
    }
}

// ---------------------------------------------------------------------------
// Split conversions for the bf16 logits GEMM
// ---------------------------------------------------------------------------
__global__ void split_w_kernel(const float* __restrict__ Wd,
                               __nv_bfloat16* __restrict__ Bhat)
{
    for (int idx = blockIdx.x * blockDim.x + threadIdx.x;
         idx < NPAD * HIDD; idx += gridDim.x * blockDim.x) {
        int n = idx >> 9, k = idx & 511;
        float x = (n < NVOCAB) ? Wd[(size_t)n * HIDD + k] : 0.f;
        __nv_bfloat16 hi = __float2bfloat16(x);
        __nv_bfloat16 lo = __float2bfloat16(x - __bfloat162float(hi));
        size_t base = (size_t)n * GK + k;
        Bhat[base]        = hi;
        Bhat[base + 512]  = lo;
        Bhat[base + 1024] = hi;
    }
}

__global__ void split_h_kernel(const float* __restrict__ H1,
                               __nv_bfloat16* __restrict__ Ahat)
{
    for (int idx = blockIdx.x * blockDim.x + threadIdx.x;
         idx < SB * HIDD; idx += gridDim.x * blockDim.x) {
        int m = idx >> 9, k = idx & 511;
        float x = H1[idx];
        __nv_bfloat16 hi = __float2bfloat16(x);
        __nv_bfloat16 lo = __float2bfloat16(x - __bfloat162float(hi));
        size_t base = (size_t)m * GK + k;
        Ahat[base]        = hi;
        Ahat[base + 512]  = hi;
        Ahat[base + 1024] = lo;
    }
}

// ---------------------------------------------------------------------------
// mma.sync (HMMA bf16) logits GEMM: out[4096, 10000] = Ahat @ Bhat^T + bd
// CTA 128x128, BK=32, 8 warps (2m x 4n), warp tile 64x32.
// cp.async double-buffered; wait-after-issue overlaps loads with compute.
// ---------------------------------------------------------------------------
#define BM 128
#define BN 128
#define BK 32
#define ASTR 40                 // bf16 units per SMEM row (80 B)
#define NIT (GK / BK)           // 48

__global__ __launch_bounds__(256)
void mma_logits(const __nv_bfloat16* __restrict__ Ahat,
                const __nv_bfloat16* __restrict__ Bhat,
                const float* __restrict__ bd,
                float* __restrict__ out)
{
    __shared__ __nv_bfloat16 As[2][BM * ASTR];
    __shared__ __nv_bfloat16 Bs[2][BN * ASTR];

    const int tid  = threadIdx.x;
    const int wid  = tid >> 5;
    const int lane = tid & 31;
    const int n0   = blockIdx.x * BN;
    const int m0   = blockIdx.y * BM;
    const int wm   = (wid & 1) * 64;
    const int wn   = (wid >> 1) * 32;

    const __nv_bfloat16* pa = Ahat + (size_t)m0 * GK;
    const __nv_bfloat16* pb = Bhat + (size_t)n0 * GK;

    const int lr  = tid >> 2;
    const int lkc = (tid & 3) << 3;
    const uint32_t asb = smem_u32(&As[0][0]);
    const uint32_t bsb = smem_u32(&Bs[0][0]);

#define GPRE(KB_, BUF_)                                                        \
    do {                                                                       \
        uint32_t ao = asb + (uint32_t)(BUF_) * (BM * ASTR * 2)                 \
                      + (uint32_t)(lr * ASTR + lkc) * 2;                       \
        uint32_t bo = bsb + (uint32_t)(BUF_) * (BN * ASTR * 2)                 \
                      + (uint32_t)(lr * ASTR + lkc) * 2;                       \
        cpa16(ao,                    pa + (size_t)lr * GK + (KB_) + lkc);      \
        cpa16(ao + 64 * ASTR * 2,    pa + (size_t)(lr + 64) * GK + (KB_) + lkc); \
        cpa16(bo,                    pb + (size_t)lr * GK + (KB_) + lkc);      \
        cpa16(bo + 64 * ASTR * 2,    pb + (size_t)(lr + 64) * GK + (KB_) + lkc); \
        CP_COMMIT();                                                           \
    } while (0)

    float4 acc[4][4];
#pragma unroll
    for (int i = 0; i < 4; ++i)
#pragma unroll
        for (int j = 0; j < 4; ++j) acc[i][j] = make_float4(0.f, 0.f, 0.f, 0.f);

    uint32_t a_off[4];
#pragma unroll
    for (int i = 0; i < 4; ++i)
        a_off[i] = ((wm + i * 16 + (lane & 15)) * ASTR + ((lane >> 4) << 3)) * 2;
    uint32_t b_off[2];
#pragma unroll
    for (int jp = 0; jp < 2; ++jp)
        b_off[jp] = ((wn + jp * 16 + (lane & 7) + ((lane >> 4) << 3)) * ASTR
                     + (((lane >> 3) & 1) << 3)) * 2;

    GPRE(0, 0);

    int buf = 0;
    for (int it = 0; it < NIT; ++it) {
        if (it + 1 < NIT) {
            GPRE((it + 1) * BK, buf ^ 1);
            CP_WAIT(1);
        } else {
            CP_WAIT(0);
        }
        __syncthreads();

        const uint32_t abase = asb + buf * (BM * ASTR * 2);
        const uint32_t bbase = bsb + buf * (BN * ASTR * 2);
#pragma unroll
        for (int ks = 0; ks < 2; ++ks) {
            const uint32_t kb = ks * 32;
            uint32_t a[4][4], b[2][4];
#pragma unroll
            for (int i = 0; i < 4; ++i)
                ldm_x4(a[i][0], a[i][1], a[i][2], a[i][3], abase + a_off[i] + kb);
#pragma unroll
            for (int jp = 0; jp < 2; ++jp)
                ldm_x4(b[jp][0], b[jp][1], b[jp][2], b[jp][3], bbase + b_off[jp] + kb);
#pragma unroll
            for (int i = 0; i < 4; ++i) {
#pragma unroll
                for (int j = 0; j < 4; ++j) {
                    const uint32_t* bj = &b[j >> 1][(j & 1) << 1];
                    mma_bf16(acc[i][j], a[i][0], a[i][1], a[i][2], a[i][3],
                             bj[0], bj[1]);
                }
            }
        }
        __syncthreads();
        buf ^= 1;
    }
#undef GPRE

    // Epilogue
#pragma unroll
    for (int i = 0; i < 4; ++i) {
        const int r0 = m0 + wm + i * 16 + (lane >> 2);
#pragma unroll
        for (int j = 0; j < 4; ++j) {
            const int col = n0 + wn + j * 8 + ((lane & 3) << 1);
            if (col < NVOCAB) {
                const float b0 = bd[col], b1 = bd[col + 1];
                float2 lo = make_float2(acc[i][j].x + b0, acc[i][j].y + b1);
                float2 hi = make_float2(acc[i][j].z + b0, acc[i][j].w + b1);
                *(float2*)(out + (size_t)r0 * NVOCAB + col)       = lo;
                *(float2*)(out + (size_t)(r0 + 8) * NVOCAB + col) = hi;
            }
        }
    }
}

__global__ void zero_ctr_kernel(int* __restrict__ ctr)
{
    int i = blockIdx.x * blockDim.x + threadIdx.x;
    if (i < 2 * S_LEN) ctr[i] = 0;
}

__global__ void finalize_kernel(const float* __restrict__ H0,
                                const float* __restrict__ H1,
                                float* __restrict__ out)
{
    int idx = blockIdx.x * blockDim.x + threadIdx.x;
    float v;
    if (idx < NBATCH * HIDD)
        v = H0[(size_t)(S_LEN - 1) * NBATCH * HIDD + idx];
    else
        v = H1[(size_t)(S_LEN - 1) * NBATCH * HIDD + (idx - NBATCH * HIDD)];
    out[(size_t)LOGITS_SZ + idx] = v;
}

// ---------------------------------------------------------------------------
extern "C" void kernel_launch(void* const* d_in, const int* in_sizes, int n_in,
                              void* d_out, int out_size)
{
    const int*   tok    = (const int*)  d_in[0];
    const float* hidden = (const float*)d_in[1];
    const float* emb    = (const float*)d_in[2];
    const float* W0     = (const float*)d_in[3];
    const float* bW0    = (const float*)d_in[4];
    const float* W1     = (const float*)d_in[5];
    const float* bW1    = (const float*)d_in[6];
    const float* U0     = (const float*)d_in[7];
    const float* bU0    = (const float*)d_in[8];
    const float* U1     = (const float*)d_in[9];
    const float* bU1    = (const float*)d_in[10];
    const float* Wd     = (const float*)d_in[11];
    const float* bd     = (const float*)d_in[12];
    float* out = (float*)d_out;

    float *A0, *H0, *A1, *H1;
    int* ctr;
    __nv_bfloat16 *Ahat, *Bhat;
    cudaGetSymbolAddress((void**)&A0, g_A0);
    cudaGetSymbolAddress((void**)&H0, g_H0);
    cudaGetSymbolAddress((void**)&A1, g_A1);
    cudaGetSymbolAddress((void**)&H1, g_H1);
    cudaGetSymbolAddress((void**)&ctr, g_ctr);
    cudaGetSymbolAddress((void**)&Ahat, g_Ahat);
    cudaGetSymbolAddress((void**)&Bhat, g_Bhat);

    zero_ctr_kernel<<<1, 128>>>(ctr);

    // Weight split for logits (independent of recurrence; launch early)
    split_w_kernel<<<512, 256>>>(Wd, Bhat);

    // A0 = emb[tok] @ W0^T + bW0 + bU0
    sgemm_nt<true><<<dim3(4, 32), 256>>>(emb, tok, W0, bW0, bU0, A0,
                                         HIDD, EMBD, HIDD);

    // layer-0 recurrence (persistent)
    rnn_layer<<<RCTAS, 256>>>(hidden, U0, A0, H0, ctr);

    // A1 = H0 @ W1^T + bW1 + bU1
    sgemm_nt<false><<<dim3(4, 32), 256>>>(H0, nullptr, W1, bW1, bU1, A1,
                                          HIDD, HIDD, HIDD);

    // layer-1 recurrence (persistent)
    rnn_layer<<<RCTAS, 256>>>(hidden + NBATCH * HIDD, U1, A1, H1,
                              ctr + S_LEN);

    // H1 split, then tensor-core (mma.sync) logits GEMM
    split_h_kernel<<<512, 256>>>(H1, Ahat);
    mma_logits<<<dim3(NPAD / BN, SB / BM), 256>>>(Ahat, Bhat, bd, out);

    // h_final
    if (out_size >= LOGITS_SZ + HFIN_SZ)
        finalize_kernel<<<HFIN_SZ / 256, 256>>>(H0, H1, out);
}

// round 11
// speedup vs baseline: 1.4610x; 1.4610x over previous
#include <cuda_runtime.h>
#include <cuda_bf16.h>
#include <cstdint>

// Problem constants
#define S_LEN   64
#define NBATCH  64
#define EMBD    512
#define HIDD    512
#define NVOCAB  10000
#define SB      4096            // S_LEN * NBATCH
#define LOGITS_SZ 40960000      // SB * NVOCAB
#define HFIN_SZ   65536         // 2 * NBATCH * HIDD

#define FCTAS   128             // fused recurrence CTAs (64 L0 + 64 L1)

// Split-GEMM dims
#define GK      1536            // 3 * HIDD
#define NPAD    10240

// Scratch (device globals: no cudaMalloc allowed)
__device__ float g_A0[SB * HIDD];
__device__ float g_H0[SB * HIDD];
__device__ float g_H1[SB * HIDD];
__device__ int   g_flag[FCTAS];
__device__ __nv_bfloat16 g_Ahat[SB * GK];       // [Hhi | Hhi | Hlo]
__device__ __nv_bfloat16 g_Bhat[NPAD * GK];     // [Whi | Wlo | Whi]

// Single dynamic-SMEM symbol (fused_rnn)
extern __shared__ __align__(16) char dynsmem[];

static __device__ __forceinline__ uint32_t smem_u32(const void* p) {
    uint32_t a;
    asm("{ .reg .u64 t; cvta.to.shared.u64 t, %1; cvt.u32.u64 %0, t; }"
        : "=r"(a) : "l"(p));
    return a;
}
static __device__ __forceinline__ void cpa16(uint32_t dst, const void* src) {
    asm volatile("cp.async.cg.shared.global [%0], [%1], 16;"
                 :: "r"(dst), "l"(src));
}
#define CP_COMMIT() asm volatile("cp.async.commit_group;")
#define CP_WAIT(N_) asm volatile("cp.async.wait_group %0;" :: "n"(N_))

static __device__ __forceinline__ void ldm_x4(uint32_t& r0, uint32_t& r1,
                                              uint32_t& r2, uint32_t& r3,
                                              uint32_t addr) {
    asm volatile("ldmatrix.sync.aligned.m8n8.x4.shared.b16 {%0,%1,%2,%3}, [%4];"
                 : "=r"(r0), "=r"(r1), "=r"(r2), "=r"(r3) : "r"(addr));
}
static __device__ __forceinline__ void mma_bf16(float4& d,
                                                uint32_t a0, uint32_t a1,
                                                uint32_t a2, uint32_t a3,
                                                uint32_t b0, uint32_t b1) {
    asm volatile("mma.sync.aligned.m16n8k16.row.col.f32.bf16.bf16.f32 "
                 "{%0,%1,%2,%3}, {%4,%5,%6,%7}, {%8,%9}, {%0,%1,%2,%3};"
                 : "+f"(d.x), "+f"(d.y), "+f"(d.z), "+f"(d.w)
                 : "r"(a0), "r"(a1), "r"(a2), "r"(a3), "r"(b0), "r"(b1));
}

// ---------------------------------------------------------------------------
// Generic NT SGEMM (fp32) for the A0 precompute.
// ---------------------------------------------------------------------------
template <bool GATHER>
__global__ __launch_bounds__(256)
void sgemm_nt(const float* __restrict__ A, const int* __restrict__ tok,
              const float* __restrict__ B,
              const float* __restrict__ bias1, const float* __restrict__ bias2,
              float* __restrict__ C, int N, int K, int ldc)
{
    __shared__ float As[2][16 * 128];
    __shared__ float Bs[2][16 * 128];

    const int tid = threadIdx.x;
    const int m0  = blockIdx.y * 128;
    const int n0  = blockIdx.x * 128;
    const int tx  = tid & 15;
    const int ty  = tid >> 4;

    const int row0 = tid >> 2;
    const int row1 = row0 + 64;
    const int kq   = (tid & 3) << 2;

    const float* pa0 = GATHER ? (A + (size_t)tok[m0 + row0] * K)
                              : (A + (size_t)(m0 + row0) * K);
    const float* pa1 = GATHER ? (A + (size_t)tok[m0 + row1] * K)
                              : (A + (size_t)(m0 + row1) * K);
    const int gc0 = n0 + row0, gc1 = n0 + row1;
    const float* pb0 = B + (size_t)gc0 * K;
    const float* pb1 = B + (size_t)gc1 * K;
    const bool  v0 = (gc0 < N), v1 = (gc1 < N);

    float4 aR0, aR1, bR0, bR1;

#define LOAD_TILES(K0_)                                                        \
    do {                                                                       \
        aR0 = *(const float4*)(pa0 + (K0_) + kq);                              \
        aR1 = *(const float4*)(pa1 + (K0_) + kq);                              \
        bR0 = v0 ? *(const float4*)(pb0 + (K0_) + kq)                          \
                 : make_float4(0.f, 0.f, 0.f, 0.f);                            \
        bR1 = v1 ? *(const float4*)(pb1 + (K0_) + kq)                          \
                 : make_float4(0.f, 0.f, 0.f, 0.f);                            \
    } while (0)

#define STORE_TILES(BUF_)                                                      \
    do {                                                                       \
        float* Ad = As[BUF_];                                                  \
        float* Bd = Bs[BUF_];                                                  \
        {                                                                      \
            int ph = ((row0 >> 2) ^ (kq >> 2));                                \
            int b  = kq * 128 + (ph << 2) + (row0 & 3);                        \
            Ad[b] = aR0.x; Ad[b + 128] = aR0.y;                                \
            Ad[b + 256] = aR0.z; Ad[b + 384] = aR0.w;                          \
            Bd[b] = bR0.x; Bd[b + 128] = bR0.y;                                \
            Bd[b + 256] = bR0.z; Bd[b + 384] = bR0.w;                          \
        }                                                                      \
        {                                                                      \
            int ph = ((row1 >> 2) ^ (kq >> 2));                                \
            int b  = kq * 128 + (ph << 2) + (row1 & 3);                        \
            Ad[b] = aR1.x; Ad[b + 128] = aR1.y;                                \
            Ad[b + 256] = aR1.z; Ad[b + 384] = aR1.w;                          \
            Bd[b] = bR1.x; Bd[b + 128] = bR1.y;                                \
            Bd[b + 256] = bR1.z; Bd[b + 384] = bR1.w;                          \
        }                                                                      \
    } while (0)

    float acc[8][8];
#pragma unroll
    for (int i = 0; i < 8; ++i)
#pragma unroll
        for (int j = 0; j < 8; ++j) acc[i][j] = 0.f;

    LOAD_TILES(0);
    STORE_TILES(0);
    __syncthreads();

    int buf = 0;
    for (int k0 = 0; k0 < K; k0 += 16) {
        const int kn = k0 + 16;
        if (kn < K) LOAD_TILES(kn);

        const float* Ac = As[buf];
        const float* Bc = Bs[buf];
#pragma unroll
        for (int kk = 0; kk < 16; ++kk) {
            const int x = (kk >> 2);
            float4 a0 = *(const float4*)(Ac + kk * 128 + ((((ty << 1))     ^ x) << 2));
            float4 a1 = *(const float4*)(Ac + kk * 128 + ((((ty << 1) + 1) ^ x) << 2));
            float4 b0 = *(const float4*)(Bc + kk * 128 + ((((tx << 1))     ^ x) << 2));
            float4 b1 = *(const float4*)(Bc + kk * 128 + ((((tx << 1) + 1) ^ x) << 2));
            float av[8] = {a0.x, a0.y, a0.z, a0.w, a1.x, a1.y, a1.z, a1.w};
            float bv[8] = {b0.x, b0.y, b0.z, b0.w, b1.x, b1.y, b1.z, b1.w};
#pragma unroll
            for (int i = 0; i < 8; ++i)
#pragma unroll
                for (int j = 0; j < 8; ++j)
                    acc[i][j] = fmaf(av[i], bv[j], acc[i][j]);
        }

        if (kn < K) STORE_TILES(buf ^ 1);
        __syncthreads();
        buf ^= 1;
    }
#undef LOAD_TILES
#undef STORE_TILES

    float badd[8];
#pragma unroll
    for (int j = 0; j < 8; ++j) {
        int c = n0 + (tx << 3) + j;
        float b = 0.f;
        if (c < N) {
            b = bias1[c];
            if (bias2) b += bias2[c];
        }
        badd[j] = b;
    }

#pragma unroll
    for (int i = 0; i < 8; ++i) {
        float* crow = C + (size_t)(m0 + (ty << 3) + i) * ldc + n0 + (tx << 3);
        float4 w0 = make_float4(acc[i][0] + badd[0], acc[i][1] + badd[1],
                                acc[i][2] + badd[2], acc[i][3] + badd[3]);
        float4 w1 = make_float4(acc[i][4] + badd[4], acc[i][5] + badd[5],
                                acc[i][6] + badd[6], acc[i][7] + badd[7]);
        *(float4*)(crow)     = w0;
        *(float4*)(crow + 4) = w1;
    }
}

// ---------------------------------------------------------------------------
// Fused 2-layer persistent recurrence, software-pipelined across layers.
// 128 CTAs: bid<64 -> layer0 cols [8b,8b+8); bid>=64 -> layer1 cols.
// Round r (0..64): L0 computes H0[r] (r<64); L1 computes H1[r-1] (r>=1)
// as tanh(bias + [H0[r-1's step] | H1[t-1]] @ [W1|U1]^T), K=1024.
// Weights SMEM-resident; H staged in 64x256 chunks via double-buffered
// cp.async. Grid barrier: per-CTA monotonic flag + single-warp poll.
// SMEM: Ws 8x1028 (32.9KB) + 2 chunk buffers 64x260 (66.6KB each) = 166KB.
// 128 CTAs x 166KB -> 1 CTA/SM on 128 of 148 SMs: all co-resident.
// ---------------------------------------------------------------------------
#define WSTR 1028
#define HCH  260
#define FSMEM_BYTES ((8 * WSTR + 2 * 64 * HCH) * 4)   // 166016

__global__ __launch_bounds__(256)
void fused_rnn(const float* __restrict__ hidden,
               const float* __restrict__ U0,
               const float* __restrict__ W1,
               const float* __restrict__ U1,
               const float* __restrict__ bW1,
               const float* __restrict__ bU1,
               const float* __restrict__ A0,
               float* __restrict__ H0,
               float* __restrict__ H1,
               int* __restrict__ flags)
{
    float* smemf = (float*)dynsmem;
    float* Ws  = smemf;                   // 8 x WSTR
    float* HsA = smemf + 8 * WSTR;        // 64 x HCH
    float* HsB = HsA + 64 * HCH;
    const uint32_t hsA = smem_u32(HsA);
    const uint32_t hsB = smem_u32(HsB);

    const int tid  = threadIdx.x;
    const int bid  = blockIdx.x;
    const bool isL1 = (bid >= 64);
    const int slot = isL1 ? (bid - 64) : bid;
    const int n0   = slot * 8;
    const int lane = tid & 31;
    const int row  = (tid >> 5) * 8 + (lane >> 2);   // 0..63
    const int c0   = (lane & 3) * 2;
    const int c1   = c0 + 1;

    // Load resident weights: cols 0..511 = phase-0 matrix, 512..1023 = phase-1
    if (!isL1) {
#pragma unroll
        for (int l = 0; l < 4; ++l) {
            int idx = tid + l * 256;
            int j = idx >> 7, kk = (idx & 127) << 2;
            *(float4*)(Ws + j * WSTR + kk) =
                *(const float4*)(U0 + (size_t)(n0 + j) * HIDD + kk);
        }
    } else {
#pragma unroll
        for (int l = 0; l < 4; ++l) {
            int idx = tid + l * 256;
            int j = idx >> 7, kk = (idx & 127) << 2;
            *(float4*)(Ws + j * WSTR + kk) =
                *(const float4*)(W1 + (size_t)(n0 + j) * HIDD + kk);
            *(float4*)(Ws + j * WSTR + 512 + kk) =
                *(const float4*)(U1 + (size_t)(n0 + j) * HIDD + kk);
        }
    }
    float biasc0 = 0.f, biasc1 = 0.f;
    if (isL1) {
        biasc0 = bW1[n0 + c0] + bU1[n0 + c0];
        biasc1 = bW1[n0 + c1] + bU1[n0 + c1];
    }
    __syncthreads();

    const float* u0p = Ws + c0 * WSTR;
    const float* u1p = Ws + c1 * WSTR;

#define STAGE(DSTU32, SRC)                                                     \
    do {                                                                       \
        const float* _s = (SRC);                                               \
        _Pragma("unroll")                                                      \
        for (int _l = 0; _l < 16; ++_l) {                                      \
            int _idx = tid + _l * 256;                                         \
            int _r = _idx >> 6;                                                \
            int _kq = (_idx & 63) << 2;                                        \
            cpa16((DSTU32) + (uint32_t)(_r * HCH + _kq) * 4,                   \
                  _s + (size_t)_r * HIDD + _kq);                               \
        }                                                                      \
        CP_COMMIT();                                                           \
    } while (0)

#define CHUNK_FMA(HSP, WOFS)                                                   \
    do {                                                                       \
        const float* _h  = (HSP) + row * HCH;                                  \
        const float* _w0 = u0p + (WOFS);                                       \
        const float* _w1 = u1p + (WOFS);                                       \
        _Pragma("unroll 4")                                                    \
        for (int _k = 0; _k < 256; _k += 8) {                                  \
            float4 h0  = *(const float4*)(_h + _k);                            \
            float4 h1  = *(const float4*)(_h + _k + 4);                        \
            float4 w00 = *(const float4*)(_w0 + _k);                           \
            float4 w01 = *(const float4*)(_w0 + _k + 4);                       \
            float4 w10 = *(const float4*)(_w1 + _k);                           \
            float4 w11 = *(const float4*)(_w1 + _k + 4);                       \
            a00 = fmaf(h0.x, w00.x, a00); a00 = fmaf(h0.y, w00.y, a00);        \
            a00 = fmaf(h0.z, w00.z, a00); a00 = fmaf(h0.w, w00.w, a00);        \
            a10 = fmaf(h0.x, w10.x, a10); a10 = fmaf(h0.y, w10.y, a10);        \
            a10 = fmaf(h0.z, w10.z, a10); a10 = fmaf(h0.w, w10.w, a10);        \
            a01 = fmaf(h1.x, w01.x, a01); a01 = fmaf(h1.y, w01.y, a01);        \
            a01 = fmaf(h1.z, w01.z, a01); a01 = fmaf(h1.w, w01.w, a01);        \
            a11 = fmaf(h1.x, w11.x, a11); a11 = fmaf(h1.y, w11.y, a11);        \
            a11 = fmaf(h1.z, w11.z, a11); a11 = fmaf(h1.w, w11.w, a11);        \
        }                                                                      \
    } while (0)

    for (int r = 0; r <= S_LEN; ++r) {
        const bool active = isL1 ? (r >= 1) : (r < S_LEN);
        if (active) {
            const int st = isL1 ? (r - 1) : r;     // step index within layer
            const float* srcp[4];
            int nc;
            if (!isL1) {
                nc = 2;
                const float* h = st ? (H0 + (size_t)(st - 1) * NBATCH * HIDD)
                                    : hidden;
                srcp[0] = h; srcp[1] = h + 256;
            } else {
                nc = 4;
                const float* h0s = H0 + (size_t)st * NBATCH * HIDD;
                const float* h1s = st ? (H1 + (size_t)(st - 1) * NBATCH * HIDD)
                                      : (hidden + NBATCH * HIDD);
                srcp[0] = h0s; srcp[1] = h0s + 256;
                srcp[2] = h1s; srcp[3] = h1s + 256;
            }
            STAGE(hsA, srcp[0]);
            STAGE(hsB, srcp[1]);

            float a00 = 0.f, a01 = 0.f, a10 = 0.f, a11 = 0.f;
            for (int c = 0; c < nc; ++c) {
                if (c == nc - 1) { CP_WAIT(0); } else { CP_WAIT(1); }
                __syncthreads();
                CHUNK_FMA((c & 1) ? HsB : HsA, c * 256);
                __syncthreads();                 // buffer free for refill
                if (c + 2 < nc)
                    STAGE((c & 1) ? hsB : hsA, srcp[c + 2]);
            }

            const size_t base = ((size_t)(st * NBATCH + row)) * HIDD + n0;
            if (!isL1) {
                H0[base + c0] = tanhf(a00 + a01 + A0[base + c0]);
                H0[base + c1] = tanhf(a10 + a11 + A0[base + c1]);
            } else {
                H1[base + c0] = tanhf(a00 + a01 + biasc0);
                H1[base + c1] = tanhf(a10 + a11 + biasc1);
            }
        }

        if (r < S_LEN) {
            // release own stores, publish monotonic flag, single-warp poll
            __threadfence();
            __syncthreads();
            if (tid == 0)
                *(volatile int*)&flags[bid] = r + 1;
            if (tid < 32) {
                volatile int* f = flags;
                const int need = r + 1;
                for (;;) {
                    int ok = (f[lane] >= need) & (f[lane + 32] >= need) &
                             (f[lane + 64] >= need) & (f[lane + 96] >= need);
                    if (__all_sync(0xffffffffu, ok)) break;
                }
            }
            __syncthreads();
        }
    }
#undef STAGE
#undef CHUNK_FMA
}

// ---------------------------------------------------------------------------
// Split conversions for the bf16 logits GEMM
// ---------------------------------------------------------------------------
__global__ void split_w_kernel(const float* __restrict__ Wd,
                               __nv_bfloat16* __restrict__ Bhat)
{
    for (int idx = blockIdx.x * blockDim.x + threadIdx.x;
         idx < NPAD * HIDD; idx += gridDim.x * blockDim.x) {
        int n = idx >> 9, k = idx & 511;
        float x = (n < NVOCAB) ? Wd[(size_t)n * HIDD + k] : 0.f;
        __nv_bfloat16 hi = __float2bfloat16(x);
        __nv_bfloat16 lo = __float2bfloat16(x - __bfloat162float(hi));
        size_t base = (size_t)n * GK + k;
        Bhat[base]        = hi;
        Bhat[base + 512]  = lo;
        Bhat[base + 1024] = hi;
    }
}

__global__ void split_h_kernel(const float* __restrict__ H1,
                               __nv_bfloat16* __restrict__ Ahat)
{
    for (int idx = blockIdx.x * blockDim.x + threadIdx.x;
         idx < SB * HIDD; idx += gridDim.x * blockDim.x) {
        int m = idx >> 9, k = idx & 511;
        float x = H1[idx];
        __nv_bfloat16 hi = __float2bfloat16(x);
        __nv_bfloat16 lo = __float2bfloat16(x - __bfloat162float(hi));
        size_t base = (size_t)m * GK + k;
        Ahat[base]        = hi;
        Ahat[base + 512]  = hi;
        Ahat[base + 1024] = lo;
    }
}

// ---------------------------------------------------------------------------
// mma.sync (HMMA bf16) logits GEMM: out[4096, 10000] = Ahat @ Bhat^T + bd
// ---------------------------------------------------------------------------
#define BM 128
#define BN 128
#define BK 32
#define ASTR 40
#define NIT (GK / BK)           // 48
#define NXT 79                  // ceil(10000/128)

__global__ __launch_bounds__(256)
void mma_logits(const __nv_bfloat16* __restrict__ Ahat,
                const __nv_bfloat16* __restrict__ Bhat,
                const float* __restrict__ bd,
                float* __restrict__ out)
{
    __shared__ __nv_bfloat16 As[2][BM * ASTR];
    __shared__ __nv_bfloat16 Bs[2][BN * ASTR];

    const int tid  = threadIdx.x;
    const int wid  = tid >> 5;
    const int lane = tid & 31;
    const int n0   = blockIdx.x * BN;
    const int m0   = blockIdx.y * BM;
    const int wm   = (wid & 1) * 64;
    const int wn   = (wid >> 1) * 32;

    const __nv_bfloat16* pa = Ahat + (size_t)m0 * GK;
    const __nv_bfloat16* pb = Bhat + (size_t)n0 * GK;

    const int lr  = tid >> 2;
    const int lkc = (tid & 3) << 3;
    const uint32_t asb = smem_u32(&As[0][0]);
    const uint32_t bsb = smem_u32(&Bs[0][0]);

#define GPRE(KB_, BUF_)                                                        \
    do {                                                                       \
        uint32_t ao = asb + (uint32_t)(BUF_) * (BM * ASTR * 2)                 \
                      + (uint32_t)(lr * ASTR + lkc) * 2;                       \
        uint32_t bo = bsb + (uint32_t)(BUF_) * (BN * ASTR * 2)                 \
                      + (uint32_t)(lr * ASTR + lkc) * 2;                       \
        cpa16(ao,                 pa + (size_t)lr * GK + (KB_) + lkc);         \
        cpa16(ao + 64 * ASTR * 2, pa + (size_t)(lr + 64) * GK + (KB_) + lkc);  \
        cpa16(bo,                 pb + (size_t)lr * GK + (KB_) + lkc);         \
        cpa16(bo + 64 * ASTR * 2, pb + (size_t)(lr + 64) * GK + (KB_) + lkc);  \
        CP_COMMIT();                                                           \
    } while (0)

    float4 acc[4][4];
#pragma unroll
    for (int i = 0; i < 4; ++i)
#pragma unroll
        for (int j = 0; j < 4; ++j) acc[i][j] = make_float4(0.f, 0.f, 0.f, 0.f);

    uint32_t a_off[4];
#pragma unroll
    for (int i = 0; i < 4; ++i)
        a_off[i] = ((wm + i * 16 + (lane & 15)) * ASTR + ((lane >> 4) << 3)) * 2;
    uint32_t b_off[2];
#pragma unroll
    for (int jp = 0; jp < 2; ++jp)
        b_off[jp] = ((wn + jp * 16 + (lane & 7) + ((lane >> 4) << 3)) * ASTR
                     + (((lane >> 3) & 1) << 3)) * 2;

    GPRE(0, 0);

    int buf = 0;
    for (int it = 0; it < NIT; ++it) {
        if (it + 1 < NIT) {
            GPRE((it + 1) * BK, buf ^ 1);
            CP_WAIT(1);
        } else {
            CP_WAIT(0);
        }
        __syncthreads();

        const uint32_t abase = asb + buf * (BM * ASTR * 2);
        const uint32_t bbase = bsb + buf * (BN * ASTR * 2);
#pragma unroll
        for (int ks = 0; ks < 2; ++ks) {
            const uint32_t kb = ks * 32;
            uint32_t a[4][4], b[2][4];
#pragma unroll
            for (int i = 0; i < 4; ++i)
                ldm_x4(a[i][0], a[i][1], a[i][2], a[i][3], abase + a_off[i] + kb);
#pragma unroll
            for (int jp = 0; jp < 2; ++jp)
                ldm_x4(b[jp][0], b[jp][1], b[jp][2], b[jp][3], bbase + b_off[jp] + kb);
#pragma unroll
            for (int i = 0; i < 4; ++i) {
#pragma unroll
                for (int j = 0; j < 4; ++j) {
                    const uint32_t* bj = &b[j >> 1][(j & 1) << 1];
                    mma_bf16(acc[i][j], a[i][0], a[i][1], a[i][2], a[i][3],
                             bj[0], bj[1]);
                }
            }
        }
        __syncthreads();
        buf ^= 1;
    }
#undef GPRE

#pragma unroll
    for (int i = 0; i < 4; ++i) {
        const int r0 = m0 + wm + i * 16 + (lane >> 2);
#pragma unroll
        for (int j = 0; j < 4; ++j) {
            const int col = n0 + wn + j * 8 + ((lane & 3) << 1);
            if (col < NVOCAB) {
                const float b0 = bd[col], b1 = bd[col + 1];
                float2 lo = make_float2(acc[i][j].x + b0, acc[i][j].y + b1);
                float2 hi = make_float2(acc[i][j].z + b0, acc[i][j].w + b1);
                *(float2*)(out + (size_t)r0 * NVOCAB + col)       = lo;
                *(float2*)(out + (size_t)(r0 + 8) * NVOCAB + col) = hi;
            }
        }
    }
}

__global__ void zero_flag_kernel(int* __restrict__ flags)
{
    int i = blockIdx.x * blockDim.x + threadIdx.x;
    if (i < FCTAS) flags[i] = 0;
}

__global__ void finalize_kernel(const float* __restrict__ H0,
                                const float* __restrict__ H1,
                                float* __restrict__ out)
{
    int idx = blockIdx.x * blockDim.x + threadIdx.x;
    float v;
    if (idx < NBATCH * HIDD)
        v = H0[(size_t)(S_LEN - 1) * NBATCH * HIDD + idx];
    else
        v = H1[(size_t)(S_LEN - 1) * NBATCH * HIDD + (idx - NBATCH * HIDD)];
    out[(size_t)LOGITS_SZ + idx] = v;
}

// ---------------------------------------------------------------------------
extern "C" void kernel_launch(void* const* d_in, const int* in_sizes, int n_in,
                              void* d_out, int out_size)
{
    const int*   tok    = (const int*)  d_in[0];
    const float* hidden = (const float*)d_in[1];
    const float* emb    = (const float*)d_in[2];
    const float* W0     = (const float*)d_in[3];
    const float* bW0    = (const float*)d_in[4];
    const float* W1     = (const float*)d_in[5];
    const float* bW1    = (const float*)d_in[6];
    const float* U0     = (const float*)d_in[7];
    const float* bU0    = (const float*)d_in[8];
    const float* U1     = (const float*)d_in[9];
    const float* bU1    = (const float*)d_in[10];
    const float* Wd     = (const float*)d_in[11];
    const float* bd     = (const float*)d_in[12];
    float* out = (float*)d_out;

    float *A0, *H0, *H1;
    int* flags;
    __nv_bfloat16 *Ahat, *Bhat;
    cudaGetSymbolAddress((void**)&A0, g_A0);
    cudaGetSymbolAddress((void**)&H0, g_H0);
    cudaGetSymbolAddress((void**)&H1, g_H1);
    cudaGetSymbolAddress((void**)&flags, g_flag);
    cudaGetSymbolAddress((void**)&Ahat, g_Ahat);
    cudaGetSymbolAddress((void**)&Bhat, g_Bhat);

    cudaFuncSetAttribute(fused_rnn,
                         cudaFuncAttributeMaxDynamicSharedMemorySize,
                         FSMEM_BYTES);

    zero_flag_kernel<<<1, 128>>>(flags);

    // Weight split for logits (independent of recurrence; launch early)
    split_w_kernel<<<512, 256>>>(Wd, Bhat);

    // A0 = emb[tok] @ W0^T + bW0 + bU0
    sgemm_nt<true><<<dim3(4, 32), 256>>>(emb, tok, W0, bW0, bU0, A0,
                                         HIDD, EMBD, HIDD);

    // Fused 2-layer recurrence (includes the former A1 GEMM)
    fused_rnn<<<FCTAS, 256, FSMEM_BYTES>>>(hidden, U0, W1, U1, bW1, bU1,
                                           A0, H0, H1, flags);

    // H1 split, then tensor-core (mma.sync) logits GEMM
    split_h_kernel<<<512, 256>>>(H1, Ahat);
    mma_logits<<<dim3(NXT, SB / BM), 256>>>(Ahat, Bhat, bd, out);

    // h_final
    if (out_size >= LOGITS_SZ + HFIN_SZ)
        finalize_kernel<<<HFIN_SZ / 256, 256>>>(H0, H1, out);
}